// round 15
// baseline (speedup 1.0000x reference)
#include <cuda_runtime.h>
#include <cstdint>

#define THRESH 0.8f
#define DECAY  0.2f

constexpr int BSZ = 256;   // batch
constexpr int CH  = 4096;  // out features
constexpr int KD  = 4096;  // in features

// Scratch: two raw half-sums per plane. g_p[z][j][b][c], z = k-half.
// Fold (p0+p1)+bias happens in lif_kernel -- identical rounding order to the
// verified reference split-K=2 fold.
__device__ float g_p[2][3 * BSZ * CH];

typedef unsigned long long u64;

__device__ __forceinline__ u64 fma2(u64 a, u64 b, u64 c) {
    u64 d; asm("fma.rn.f32x2 %0, %1, %2, %3;" : "=l"(d) : "l"(a), "l"(b), "l"(c));
    return d;
}

// ---------------- GEMM half-chains: p[z][j][m][n] = sum_{k in half z} ...
// Each output's half is an ascending fused-FMA chain from zero (verified
// reference order). f32x2 packs two ADJACENT-N outputs per instruction:
// B pairs load directly as u64 from smem; A is duplicated in smem so {a,a}
// pairs load directly too -- zero packing movs in the inner loop.
constexpr int BM = 32, BN = 128, BK = 16, TM = 4, TN = 8;  // 128 threads

__global__ __launch_bounds__(128, 4) void gemm3_kernel(
    const float* __restrict__ x,
    const float* __restrict__ W1,
    const float* __restrict__ W2,
    const float* __restrict__ W3)
{
    __shared__ float As2[2][BK][2 * BM];  // [buf][k][2m] duplicated  8 KB
    __shared__ float Bs[2][BK][BN];       // [buf][k][n]             16 KB

    const int tid = threadIdx.x;
    const int bx  = blockIdx.x;    // 0..95  (j*32 + n-tile)
    const int by  = blockIdx.y;    // 0..7   (m-tile)
    const int bz  = blockIdx.z;    // 0..1   (k-half)

    const int j  = bx >> 5;
    const int n0 = (bx & 31) * BN;
    const int m0 = by * BM;

    const float* W = (j == 0) ? W1 : (j == 1) ? W2 : W3;

    const int tx = tid & 15;       // 16 -> n quads
    const int ty = tid >> 4;       // 8  -> m quad

    // global load coords
    const int aRow = tid >> 2;               // 0..31
    const int aK   = (tid & 3) * 4;
    const float* aPtr = x + (size_t)(m0 + aRow) * KD + aK;
    const float* bPtr[4];
    #pragma unroll
    for (int l = 0; l < 4; l++) {
        int li  = tid + l * 128;
        bPtr[l] = W + (size_t)(n0 + (li >> 2)) * KD + (li & 3) * 4;
    }

    // accumulators: 4 m rows x 4 n-pairs (lane0 = n even, lane1 = n odd)
    u64 acc[TM][4];
    #pragma unroll
    for (int p = 0; p < TM; p++)
        #pragma unroll
        for (int q = 0; q < 4; q++) acc[p][q] = 0ULL;

    const int kbBeg = bz * 128;    // half = 2048 k = 128 BK-blocks
    const int kbEnd = kbBeg + 128;

    // ---- prologue: load block kbBeg into buf 0 ----
    {
        const int k0 = kbBeg * BK;
        float4 a = *(const float4*)(aPtr + k0);
        float2* ad = (float2*)&As2[0][0][2 * aRow];
        // As2 row stride = 64 floats = 32 float2
        ((float2*)&As2[0][aK + 0][2 * aRow])[0] = make_float2(a.x, a.x);
        ((float2*)&As2[0][aK + 1][2 * aRow])[0] = make_float2(a.y, a.y);
        ((float2*)&As2[0][aK + 2][2 * aRow])[0] = make_float2(a.z, a.z);
        ((float2*)&As2[0][aK + 3][2 * aRow])[0] = make_float2(a.w, a.w);
        (void)ad;
        #pragma unroll
        for (int l = 0; l < 4; l++) {
            int li  = tid + l * 128;
            int row = li >> 2;
            int kq  = (li & 3) * 4;
            float4 v = *(const float4*)(bPtr[l] + k0);
            Bs[0][kq + 0][row] = v.x; Bs[0][kq + 1][row] = v.y;
            Bs[0][kq + 2][row] = v.z; Bs[0][kq + 3][row] = v.w;
        }
    }
    __syncthreads();

    int buf = 0;
    for (int kb = kbBeg; kb < kbEnd; kb++) {
        const bool more = (kb + 1 < kbEnd);
        float4 a, bv[4];
        if (more) {
            const int k1 = (kb + 1) * BK;
            a = *(const float4*)(aPtr + k1);
            #pragma unroll
            for (int l = 0; l < 4; l++) bv[l] = *(const float4*)(bPtr[l] + k1);
        }

        // ---- compute current block ----
        #pragma unroll
        for (int kk = 0; kk < BK; kk++) {
            // A: 4 m duplicated pairs {a,a} -> 2 LDS.128 (broadcast)
            ulonglong2 aa01 = *(const ulonglong2*)(&As2[buf][kk][ty * 8]);
            ulonglong2 aa23 = *(const ulonglong2*)(&As2[buf][kk][ty * 8 + 4]);
            u64 aa[4] = { aa01.x, aa01.y, aa23.x, aa23.y };
            // B: adjacent-n pairs, direct u64 -> 2 LDS.128 (16B stride, cf)
            ulonglong2 bb01 = *(const ulonglong2*)(&Bs[buf][kk][tx * 4]);
            ulonglong2 bb23 = *(const ulonglong2*)(&Bs[buf][kk][64 + tx * 4]);
            u64 bb[4] = { bb01.x, bb01.y, bb23.x, bb23.y };
            #pragma unroll
            for (int p = 0; p < TM; p++)
                #pragma unroll
                for (int q = 0; q < 4; q++)
                    acc[p][q] = fma2(aa[p], bb[q], acc[p][q]);
        }

        // ---- stage next block into the free buffer ----
        if (more) {
            int nb = buf ^ 1;
            ((float2*)&As2[nb][aK + 0][2 * aRow])[0] = make_float2(a.x, a.x);
            ((float2*)&As2[nb][aK + 1][2 * aRow])[0] = make_float2(a.y, a.y);
            ((float2*)&As2[nb][aK + 2][2 * aRow])[0] = make_float2(a.z, a.z);
            ((float2*)&As2[nb][aK + 3][2 * aRow])[0] = make_float2(a.w, a.w);
            #pragma unroll
            for (int l = 0; l < 4; l++) {
                int li  = tid + l * 128;
                int row = li >> 2;
                int kq  = (li & 3) * 4;
                Bs[nb][kq + 0][row] = bv[l].x; Bs[nb][kq + 1][row] = bv[l].y;
                Bs[nb][kq + 2][row] = bv[l].z; Bs[nb][kq + 3][row] = bv[l].w;
            }
        }
        __syncthreads();
        buf ^= 1;
    }

    // store raw half-sums (u64 pairs are bit-identical adjacent-n floats)
    float* yp = g_p[bz] + (size_t)j * BSZ * CH;
    #pragma unroll
    for (int p = 0; p < TM; p++) {
        int m = m0 + ty * TM + p;
        float* r = yp + (size_t)m * CH + n0;
        ulonglong2 v0 = { acc[p][0], acc[p][1] };
        ulonglong2 v1 = { acc[p][2], acc[p][3] };
        *(ulonglong2*)(r + tx * 4)      = v0;
        *(ulonglong2*)(r + 64 + tx * 4) = v1;
    }
}

// ---------------- LIF recurrence + split-K fold: one thread per (b,c) -------
__global__ __launch_bounds__(256) void lif_kernel(
    const float* __restrict__ b1, const float* __restrict__ b2,
    const float* __restrict__ b3,
    const float* __restrict__ Wlif, const float* __restrict__ blif,
    const int* __restrict__ winsPtr, float* __restrict__ out)
{
    const int idx = blockIdx.x * 256 + threadIdx.x;   // = b*CH + c
    const int b = idx >> 12;          // /CH
    const int c = idx & (CH - 1);

    // fold: y = (p0 + p1) + bias, separately rounded (reference order)
    const float y0 = __fadd_rn(__fadd_rn(g_p[0][idx],
                                         g_p[1][idx]), b1[c]);
    const float y1 = __fadd_rn(__fadd_rn(g_p[0][BSZ * CH + idx],
                                         g_p[1][BSZ * CH + idx]), b2[c]);
    const float y2 = __fadd_rn(__fadd_rn(g_p[0][2 * BSZ * CH + idx],
                                         g_p[1][2 * BSZ * CH + idx]), b3[c]);

    const float w0 = Wlif[0], w1 = Wlif[1], w2 = Wlif[2];
    const float bl = blif[0];
    const int wins = *winsPtr;

    float m0 = 0.f, m1 = 0.f, m2 = 0.f, m3 = 0.f;
    float s0 = 0.f, s1 = 0.f, s2 = 0.f, s3 = 0.f;

    float* o = out + (size_t)b * wins * (CH * 4) + (size_t)c * 4;

    for (int t = 0; t < wins; t++) {
        float inner = __fadd_rn(
            __fmaf_rn(m2, w2, __fmaf_rn(m1, w1, __fmul_rn(m0, w0))), bl);
        m0 = __fadd_rn(__fmul_rn(__fmul_rn(m0, DECAY), 1.f - s0), y0);
        m1 = __fadd_rn(__fmul_rn(__fmul_rn(m1, DECAY), 1.f - s1), y1);
        m2 = __fadd_rn(__fmul_rn(__fmul_rn(m2, DECAY), 1.f - s2), y2);
        m3 = __fadd_rn(__fmul_rn(__fmul_rn(m3, DECAY), 1.f - s3), inner);
        s0 = (m0 > THRESH) ? 1.f : 0.f;
        s1 = (m1 > THRESH) ? 1.f : 0.f;
        s2 = (m2 > THRESH) ? 1.f : 0.f;
        s3 = (m3 > THRESH) ? 1.f : 0.f;
        *(float4*)(o + (size_t)t * CH * 4) = make_float4(s0, s1, s2, s3);
    }
}

// ---------------- launch ----------------------------------------------------
extern "C" void kernel_launch(void* const* d_in, const int* in_sizes, int n_in,
                              void* d_out, int out_size) {
    const float* x    = (const float*)d_in[0];
    const float* W1   = (const float*)d_in[1];
    const float* b1   = (const float*)d_in[2];
    const float* W2   = (const float*)d_in[3];
    const float* b2   = (const float*)d_in[4];
    const float* W3   = (const float*)d_in[5];
    const float* b3   = (const float*)d_in[6];
    const float* Wlif = (const float*)d_in[7];
    const float* blif = (const float*)d_in[8];
    const int*   wins = (const int*)d_in[9];

    dim3 ggrid(96, 8, 2);   // 1536 CTAs, 128 threads each
    gemm3_kernel<<<ggrid, 128>>>(x, W1, W2, W3);
    lif_kernel<<<(BSZ * CH) / 256, 256>>>(b1, b2, b3, Wlif, blif, wins,
                                          (float*)d_out);
}